// round 3
// baseline (speedup 1.0000x reference)
#include <cuda_runtime.h>

#define N_NODES 50000
#define N_EDGES 800000
#define DIM 128
#define NLAYERS 3
#define LN_EPS 1e-5f

// ---------------- device scratch (no allocs allowed) ----------------
__device__ __align__(16) float g_h[N_NODES * DIM];     // current node features
__device__ __align__(16) float g_agg[N_NODES * DIM];   // aggregation / h2 buffer
__device__ int   g_deg[N_NODES];
__device__ int   g_off[N_NODES + 1];
__device__ int   g_pos[N_NODES];
__device__ int   g_srcs[N_EDGES];
__device__ float g_inv[N_NODES];
__device__ int   g_is32;   // 1 if edge_index is int32, 0 if int64

// ---------------- init: copy x -> g_h, zero degree + flag ----------------
__global__ void k_init(const float* __restrict__ x) {
    int i = blockIdx.x * blockDim.x + threadIdx.x;
    if (i < N_NODES * DIM) g_h[i] = x[i];
    if (i < N_NODES) g_deg[i] = 0;
    if (i == 0) g_is32 = 0;
}

// ---------------- dtype detection ----------------
// If buffer is int64 with node-ids < 2^31, every odd 32-bit word is 0.
// If it is int32 (random ids over 1.6M entries), some odd word is nonzero.
__global__ void k_detect(const unsigned int* __restrict__ w) {
    int i = blockIdx.x * blockDim.x + threadIdx.x;  // over 2*N_EDGES words
    if (i < 2 * N_EDGES) {
        if ((i & 1) && w[i] != 0u) g_is32 = 1;  // racy but idempotent store of 1
    }
}

__device__ __forceinline__ int load_idx(const void* ei, long long pos) {
    if (g_is32) return ((const int*)ei)[pos];
    return (int)((const long long*)ei)[pos];
}

// ---------------- CSR build ----------------
__global__ void k_count(const void* __restrict__ ei) {
    int e = blockIdx.x * blockDim.x + threadIdx.x;
    if (e < N_EDGES) {
        int dst = load_idx(ei, (long long)N_EDGES + e);
        atomicAdd(&g_deg[dst], 1);
    }
}

__global__ void k_scan() {
    __shared__ int ssum[1024];
    const int PER = (N_NODES + 1023) / 1024;  // 49
    int t = threadIdx.x;
    int base = t * PER;
    int s = 0;
    for (int i = 0; i < PER; i++) {
        int idx = base + i;
        if (idx < N_NODES) s += g_deg[idx];
    }
    ssum[t] = s;
    __syncthreads();
    for (int off = 1; off < 1024; off <<= 1) {
        int v = (t >= off) ? ssum[t - off] : 0;
        __syncthreads();
        ssum[t] += v;
        __syncthreads();
    }
    int run = ssum[t] - s;  // exclusive start of this chunk
    for (int i = 0; i < PER; i++) {
        int idx = base + i;
        if (idx < N_NODES) {
            int d = g_deg[idx];
            g_off[idx] = run;
            g_pos[idx] = run;
            g_inv[idx] = 1.0f / (float)max(d, 1);
            run += d;
        }
    }
    if (t == 1023) g_off[N_NODES] = ssum[1023];
}

__global__ void k_fill(const void* __restrict__ ei) {
    int e = blockIdx.x * blockDim.x + threadIdx.x;
    if (e < N_EDGES) {
        int src = load_idx(ei, e);
        int dst = load_idx(ei, (long long)N_EDGES + e);
        int p = atomicAdd(&g_pos[dst], 1);
        g_srcs[p] = src;
    }
}

// ---------------- mean-neighbor aggregation: warp per node ----------------
__global__ void k_aggregate() {
    int w = (blockIdx.x * blockDim.x + threadIdx.x) >> 5;
    if (w >= N_NODES) return;
    int lane = threadIdx.x & 31;
    int beg = g_off[w], end = g_off[w + 1];
    float4 acc = make_float4(0.f, 0.f, 0.f, 0.f);
    const float* hp = g_h;
    int e = beg;
    for (; e + 4 <= end; e += 4) {
        int s0 = g_srcs[e + 0];
        int s1 = g_srcs[e + 1];
        int s2 = g_srcs[e + 2];
        int s3 = g_srcs[e + 3];
        float4 v0 = *(const float4*)(hp + s0 * DIM + lane * 4);
        float4 v1 = *(const float4*)(hp + s1 * DIM + lane * 4);
        float4 v2 = *(const float4*)(hp + s2 * DIM + lane * 4);
        float4 v3 = *(const float4*)(hp + s3 * DIM + lane * 4);
        acc.x += v0.x + v1.x + v2.x + v3.x;
        acc.y += v0.y + v1.y + v2.y + v3.y;
        acc.z += v0.z + v1.z + v2.z + v3.z;
        acc.w += v0.w + v1.w + v2.w + v3.w;
    }
    for (; e < end; e++) {
        int s0 = g_srcs[e];
        float4 v0 = *(const float4*)(hp + s0 * DIM + lane * 4);
        acc.x += v0.x; acc.y += v0.y; acc.z += v0.z; acc.w += v0.w;
    }
    float inv = g_inv[w];
    acc.x *= inv; acc.y *= inv; acc.z *= inv; acc.w *= inv;
    *(float4*)(g_agg + w * DIM + lane * 4) = acc;
}

// ---------------- fused dual GEMM: h2 = agg@Wl^T + h@Wr^T + b --------------
// BM=128, BN=128, 512 threads, static shared only (~33 KB).
__global__ void __launch_bounds__(512)
k_gemm(const float* __restrict__ Wl, const float* __restrict__ Wr,
       const float* __restrict__ bias) {
    __shared__ float sA[128 * 32];   // 16384 B
    __shared__ float sB[32 * 132];   // 16896 B

    int tid = threadIdx.x;
    int ty = tid >> 5;   // 0..15
    int tx = tid & 31;   // 0..31
    int m0 = blockIdx.x * 128;

    float acc[8][4];
#pragma unroll
    for (int i = 0; i < 8; i++)
#pragma unroll
        for (int j = 0; j < 4; j++) acc[i][j] = 0.f;

#pragma unroll
    for (int phase = 0; phase < 2; phase++) {
        const float* A = phase ? g_h : g_agg;
        const float* W = phase ? Wr : Wl;
#pragma unroll
        for (int kc = 0; kc < 4; kc++) {
            for (int i = tid; i < 128 * 8; i += 512) {
                int m = i >> 3;   // 0..127
                int q = i & 7;    // 0..7 col-quad
                float4 v = make_float4(0.f, 0.f, 0.f, 0.f);
                if (m0 + m < N_NODES)
                    v = *(const float4*)(A + (m0 + m) * DIM + kc * 32 + q * 4);
                *(float4*)(sA + m * 32 + q * 4) = v;
            }
            for (int i = tid; i < 32 * 128; i += 512) {
                int n = i >> 5;   // 0..127
                int k = i & 31;   // 0..31
                sB[k * 132 + n] = W[n * 128 + kc * 32 + k];
            }
            __syncthreads();
#pragma unroll 8
            for (int k = 0; k < 32; k++) {
                float4 b = *(const float4*)(sB + k * 132 + tx * 4);
#pragma unroll
                for (int i = 0; i < 8; i++) {
                    float a = sA[(ty * 8 + i) * 32 + k];
                    acc[i][0] = fmaf(a, b.x, acc[i][0]);
                    acc[i][1] = fmaf(a, b.y, acc[i][1]);
                    acc[i][2] = fmaf(a, b.z, acc[i][2]);
                    acc[i][3] = fmaf(a, b.w, acc[i][3]);
                }
            }
            __syncthreads();
        }
    }

    float4 bb = *(const float4*)(bias + tx * 4);
#pragma unroll
    for (int i = 0; i < 8; i++) {
        int m = m0 + ty * 8 + i;
        if (m < N_NODES) {
            float4 o;
            o.x = acc[i][0] + bb.x;
            o.y = acc[i][1] + bb.y;
            o.z = acc[i][2] + bb.z;
            o.w = acc[i][3] + bb.w;
            *(float4*)(g_agg + m * DIM + tx * 4) = o;
        }
    }
}

// ---------------- LayerNorm + ReLU: warp per row ----------------
__global__ void k_ln_relu(const float* __restrict__ gamma,
                          const float* __restrict__ beta,
                          float* __restrict__ out_final) {
    int w = (blockIdx.x * blockDim.x + threadIdx.x) >> 5;
    if (w >= N_NODES) return;
    int lane = threadIdx.x & 31;
    float4 v = *(const float4*)(g_agg + w * DIM + lane * 4);
    float s = v.x + v.y + v.z + v.w;
#pragma unroll
    for (int o = 16; o; o >>= 1) s += __shfl_xor_sync(0xffffffffu, s, o);
    float mu = s * (1.0f / 128.0f);
    float dx = v.x - mu, dy = v.y - mu, dz = v.z - mu, dw = v.w - mu;
    float q = dx * dx + dy * dy + dz * dz + dw * dw;
#pragma unroll
    for (int o = 16; o; o >>= 1) q += __shfl_xor_sync(0xffffffffu, q, o);
    float rs = rsqrtf(q * (1.0f / 128.0f) + LN_EPS);
    float4 g = *(const float4*)(gamma + lane * 4);
    float4 b = *(const float4*)(beta + lane * 4);
    float4 o;
    o.x = fmaxf(dx * rs * g.x + b.x, 0.f);
    o.y = fmaxf(dy * rs * g.y + b.y, 0.f);
    o.z = fmaxf(dz * rs * g.z + b.z, 0.f);
    o.w = fmaxf(dw * rs * g.w + b.w, 0.f);
    float* dst = out_final ? out_final : g_h;
    *(float4*)(dst + w * DIM + lane * 4) = o;
}

// ---------------- launch ----------------
extern "C" void kernel_launch(void* const* d_in, const int* in_sizes, int n_in,
                              void* d_out, int out_size) {
    const float* x     = (const float*)d_in[0];
    const void*  ei    = d_in[1];
    const float* Wl    = (const float*)d_in[2];
    const float* bl    = (const float*)d_in[3];
    const float* Wr    = (const float*)d_in[4];
    const float* gamma = (const float*)d_in[5];
    const float* beta  = (const float*)d_in[6];
    float* out = (float*)d_out;

    k_init<<<(N_NODES * DIM + 255) / 256, 256>>>(x);
    k_detect<<<(2 * N_EDGES + 255) / 256, 256>>>((const unsigned int*)ei);
    k_count<<<(N_EDGES + 255) / 256, 256>>>(ei);
    k_scan<<<1, 1024>>>();
    k_fill<<<(N_EDGES + 255) / 256, 256>>>(ei);

    for (int l = 0; l < NLAYERS; l++) {
        k_aggregate<<<(N_NODES + 7) / 8, 256>>>();
        k_gemm<<<(N_NODES + 127) / 128, 512>>>(
            Wl + l * DIM * DIM, Wr + l * DIM * DIM, bl + l * DIM);
        k_ln_relu<<<(N_NODES + 7) / 8, 256>>>(
            gamma + l * DIM, beta + l * DIM,
            (l == NLAYERS - 1) ? out : (float*)nullptr);
    }
}

// round 4
// speedup vs baseline: 1.1940x; 1.1940x over previous
#include <cuda_runtime.h>

#define N_NODES 50000
#define N_EDGES 800000
#define DIM 128
#define NLAYERS 3
#define LN_EPS 1e-5f
#define SCAN_BLOCKS 49   // ceil(50000/1024)

typedef unsigned long long ull;

// ---------------- device scratch (no allocs allowed) ----------------
__device__ __align__(16) float g_h[N_NODES * DIM];
__device__ __align__(16) float g_agg[N_NODES * DIM];
__device__ int   g_deg[N_NODES];
__device__ int   g_off[N_NODES + 1];
__device__ int   g_pos[N_NODES];
__device__ int   g_srcs[N_EDGES];
__device__ float g_inv[N_NODES];
__device__ int   g_bsum[SCAN_BLOCKS];
__device__ int   g_is32;

// ---------------- zero deg + flag ----------------
__global__ void k_zero() {
    int i = blockIdx.x * blockDim.x + threadIdx.x;
    if (i < N_NODES) g_deg[i] = 0;
    if (i == 0) g_is32 = 0;
}

// ---------------- dtype detection (int64 vs int32 edge_index) ----------------
__global__ void k_detect(const unsigned int* __restrict__ w) {
    int i = blockIdx.x * blockDim.x + threadIdx.x;
    if (i < 2 * N_EDGES) {
        if ((i & 1) && w[i] != 0u) g_is32 = 1;  // idempotent
    }
}

__device__ __forceinline__ int load_idx(const void* ei, long long pos) {
    if (g_is32) return ((const int*)ei)[pos];
    return (int)((const long long*)ei)[pos];
}

// ---------------- CSR build ----------------
__global__ void k_count(const void* __restrict__ ei) {
    int e = blockIdx.x * blockDim.x + threadIdx.x;
    if (e < N_EDGES) {
        int dst = load_idx(ei, (long long)N_EDGES + e);
        atomicAdd(&g_deg[dst], 1);
    }
}

// phase 1: per-block sums of degree
__global__ void k_bsum() {
    __shared__ int sred[32];
    int b = blockIdx.x, t = threadIdx.x;
    int i = b * 1024 + t;
    int v = (i < N_NODES) ? g_deg[i] : 0;
#pragma unroll
    for (int o = 16; o; o >>= 1) v += __shfl_xor_sync(0xffffffffu, v, o);
    if ((t & 31) == 0) sred[t >> 5] = v;
    __syncthreads();
    if (t < 32) {
        int s = sred[t];
#pragma unroll
        for (int o = 16; o; o >>= 1) s += __shfl_xor_sync(0xffffffffu, s, o);
        if (t == 0) g_bsum[b] = s;
    }
}

// phase 2: serial exclusive scan of 49 block sums (trivial)
__global__ void k_scanb() {
    int run = 0;
    for (int b = 0; b < SCAN_BLOCKS; b++) {
        int s = g_bsum[b];
        g_bsum[b] = run;
        run += s;
    }
    g_off[N_NODES] = run;
}

// phase 3: intra-block exclusive scan + write offsets
__global__ void k_apply() {
    __shared__ int ss[1024];
    int b = blockIdx.x, t = threadIdx.x;
    int i = b * 1024 + t;
    int d = (i < N_NODES) ? g_deg[i] : 0;
    ss[t] = d;
    __syncthreads();
#pragma unroll
    for (int off = 1; off < 1024; off <<= 1) {
        int v = (t >= off) ? ss[t - off] : 0;
        __syncthreads();
        ss[t] += v;
        __syncthreads();
    }
    if (i < N_NODES) {
        int excl = ss[t] - d + g_bsum[b];
        g_off[i] = excl;
        g_pos[i] = excl;
        g_inv[i] = 1.0f / (float)max(d, 1);
    }
}

__global__ void k_fill(const void* __restrict__ ei) {
    int e = blockIdx.x * blockDim.x + threadIdx.x;
    if (e < N_EDGES) {
        int src = load_idx(ei, e);
        int dst = load_idx(ei, (long long)N_EDGES + e);
        int p = atomicAdd(&g_pos[dst], 1);
        g_srcs[p] = src;
    }
}

// ---------------- mean-neighbor aggregation: warp per node ----------------
__global__ void k_aggregate(const float* __restrict__ hp) {
    int w = (blockIdx.x * blockDim.x + threadIdx.x) >> 5;
    if (w >= N_NODES) return;
    int lane = threadIdx.x & 31;
    int beg = g_off[w], end = g_off[w + 1];
    float4 acc = make_float4(0.f, 0.f, 0.f, 0.f);
    int e = beg;
    for (; e + 8 <= end; e += 8) {
        float4 v[8];
#pragma unroll
        for (int u = 0; u < 8; u++) {
            int s = g_srcs[e + u];
            v[u] = __ldg((const float4*)(hp + (long long)s * DIM + lane * 4));
        }
#pragma unroll
        for (int u = 0; u < 8; u++) {
            acc.x += v[u].x; acc.y += v[u].y; acc.z += v[u].z; acc.w += v[u].w;
        }
    }
    for (; e < end; e++) {
        int s = g_srcs[e];
        float4 v = __ldg((const float4*)(hp + (long long)s * DIM + lane * 4));
        acc.x += v.x; acc.y += v.y; acc.z += v.z; acc.w += v.w;
    }
    float inv = g_inv[w];
    acc.x *= inv; acc.y *= inv; acc.z *= inv; acc.w *= inv;
    *(float4*)(g_agg + (long long)w * DIM + lane * 4) = acc;
}

// ---------------- packed f32x2 helpers ----------------
__device__ __forceinline__ ull fma2(ull a, ull b, ull c) {
    asm("fma.rn.f32x2 %0, %1, %2, %0;" : "+l"(c) : "l"(a), "l"(b));
    return c;
}
__device__ __forceinline__ float2 up2(ull v) {
    float2 r;
    asm("mov.b64 {%0, %1}, %2;" : "=f"(r.x), "=f"(r.y) : "l"(v));
    return r;
}

// ---------------- fused dual GEMM + bias + LayerNorm + ReLU ----------------
// h2 = agg@Wl^T + A2@Wr^T + b; out = relu(LN(h2))
// BM=128, BN=128, 512 threads. Weight smem is k-pair interleaved so both a
// and b operands of fma.rn.f32x2 are natural 64-bit vector loads (no packs).
__global__ void __launch_bounds__(512)
k_gemm_ln(const float* __restrict__ A2, const float* __restrict__ Wl,
          const float* __restrict__ Wr, const float* __restrict__ bias,
          const float* __restrict__ gamma, const float* __restrict__ beta,
          float* __restrict__ dst) {
    __shared__ __align__(16) float sA[128 * 32];   // A chunk [m][k]
    __shared__ __align__(16) float sB[16 * 264];   // W chunk: [(k>>1)][n*2+(k&1)]

    int tid = threadIdx.x;
    int ty = tid >> 5;   // warp id 0..15 -> rows ty*8..ty*8+7
    int tx = tid & 31;   // lane -> cols tx*4..tx*4+3
    int m0 = blockIdx.x * 128;

    ull acc[8][4];
#pragma unroll
    for (int i = 0; i < 8; i++)
#pragma unroll
        for (int j = 0; j < 4; j++) acc[i][j] = 0ull;

#pragma unroll
    for (int phase = 0; phase < 2; phase++) {
        const float* A = phase ? A2 : g_agg;
        const float* W = phase ? Wr : Wl;
#pragma unroll
        for (int kc = 0; kc < 4; kc++) {
            // A chunk: 128 rows x 32 cols
            for (int i = tid; i < 128 * 8; i += 512) {
                int m = i >> 3;
                int q = i & 7;
                float4 v = make_float4(0.f, 0.f, 0.f, 0.f);
                if (m0 + m < N_NODES)
                    v = *(const float4*)(A + (long long)(m0 + m) * DIM + kc * 32 + q * 4);
                *(float4*)(sA + m * 32 + q * 4) = v;
            }
            // W chunk, transposed + k-pair interleaved
            for (int i = tid; i < 32 * 128; i += 512) {
                int n = i >> 5;
                int k = i & 31;
                sB[(k >> 1) * 264 + n * 2 + (k & 1)] = W[n * 128 + kc * 32 + k];
            }
            __syncthreads();
#pragma unroll
            for (int kp = 0; kp < 16; kp++) {
                ulonglong2 b01 = *(const ulonglong2*)(sB + kp * 264 + tx * 8);
                ulonglong2 b23 = *(const ulonglong2*)(sB + kp * 264 + tx * 8 + 4);
#pragma unroll
                for (int i = 0; i < 8; i++) {
                    ull a = *(const ull*)(sA + (ty * 8 + i) * 32 + kp * 2);
                    acc[i][0] = fma2(a, b01.x, acc[i][0]);
                    acc[i][1] = fma2(a, b01.y, acc[i][1]);
                    acc[i][2] = fma2(a, b23.x, acc[i][2]);
                    acc[i][3] = fma2(a, b23.y, acc[i][3]);
                }
            }
            __syncthreads();
        }
    }

    // epilogue: horizontal add, +bias, LayerNorm (warp owns full row), ReLU
    float4 bb = *(const float4*)(bias + tx * 4);
    float4 gg = *(const float4*)(gamma + tx * 4);
    float4 be = *(const float4*)(beta + tx * 4);
#pragma unroll
    for (int i = 0; i < 8; i++) {
        int m = m0 + ty * 8 + i;         // uniform across warp
        if (m >= N_NODES) continue;
        float2 p0 = up2(acc[i][0]);
        float2 p1 = up2(acc[i][1]);
        float2 p2 = up2(acc[i][2]);
        float2 p3 = up2(acc[i][3]);
        float d0 = p0.x + p0.y + bb.x;
        float d1 = p1.x + p1.y + bb.y;
        float d2 = p2.x + p2.y + bb.z;
        float d3 = p3.x + p3.y + bb.w;
        float s = d0 + d1 + d2 + d3;
#pragma unroll
        for (int o = 16; o; o >>= 1) s += __shfl_xor_sync(0xffffffffu, s, o);
        float mu = s * (1.0f / 128.0f);
        float e0 = d0 - mu, e1 = d1 - mu, e2 = d2 - mu, e3 = d3 - mu;
        float q = e0 * e0 + e1 * e1 + e2 * e2 + e3 * e3;
#pragma unroll
        for (int o = 16; o; o >>= 1) q += __shfl_xor_sync(0xffffffffu, q, o);
        float rs = rsqrtf(q * (1.0f / 128.0f) + LN_EPS);
        float4 o4;
        o4.x = fmaxf(e0 * rs * gg.x + be.x, 0.f);
        o4.y = fmaxf(e1 * rs * gg.y + be.y, 0.f);
        o4.z = fmaxf(e2 * rs * gg.z + be.z, 0.f);
        o4.w = fmaxf(e3 * rs * gg.w + be.w, 0.f);
        *(float4*)(dst + (long long)m * DIM + tx * 4) = o4;
    }
}

// ---------------- launch ----------------
extern "C" void kernel_launch(void* const* d_in, const int* in_sizes, int n_in,
                              void* d_out, int out_size) {
    const float* x     = (const float*)d_in[0];
    const void*  ei    = d_in[1];
    const float* Wl    = (const float*)d_in[2];
    const float* bl    = (const float*)d_in[3];
    const float* Wr    = (const float*)d_in[4];
    const float* gamma = (const float*)d_in[5];
    const float* beta  = (const float*)d_in[6];
    float* out = (float*)d_out;

    k_zero<<<(N_NODES + 255) / 256, 256>>>();
    k_detect<<<(2 * N_EDGES + 255) / 256, 256>>>((const unsigned int*)ei);
    k_count<<<(N_EDGES + 255) / 256, 256>>>(ei);
    k_bsum<<<SCAN_BLOCKS, 1024>>>();
    k_scanb<<<1, 1>>>();
    k_apply<<<SCAN_BLOCKS, 1024>>>();
    k_fill<<<(N_EDGES + 255) / 256, 256>>>(ei);

    for (int l = 0; l < NLAYERS; l++) {
        const float* hsrc = (l == 0) ? x : g_h;   // device-symbol decay OK in device code only
        // NOTE: can't take g_h address on host directly; pass via kernels below.
        // aggregate: layer 0 gathers from x, else from g_h
        if (l == 0) {
            k_aggregate<<<(N_NODES + 7) / 8, 256>>>(x);
        } else {
            // get device pointer to g_h via a launch-time trick: use a kernel arg of nullptr
            // and read g_h inside? Simpler: obtain address with cudaGetSymbolAddress is not
            // graph-unsafe (host API, no alloc) and runs before capture too.
            static float* hdev = nullptr;
            if (!hdev) cudaGetSymbolAddress((void**)&hdev, g_h);
            k_aggregate<<<(N_NODES + 7) / 8, 256>>>(hdev);
        }
        static float* hdev2 = nullptr;
        if (!hdev2) cudaGetSymbolAddress((void**)&hdev2, g_h);
        const float* A2 = (l == 0) ? x : hdev2;
        float* dst = (l == NLAYERS - 1) ? out : hdev2;
        k_gemm_ln<<<(N_NODES + 127) / 128, 512>>>(
            A2, Wl + l * DIM * DIM, Wr + l * DIM * DIM, bl + l * DIM,
            gamma + l * DIM, beta + l * DIM, dst);
    }
}

// round 5
// speedup vs baseline: 1.2238x; 1.0250x over previous
#include <cuda_runtime.h>
#include <cstdint>

#define N_NODES 50000
#define N_EDGES 800000
#define DIM 128
#define NLAYERS 3
#define LN_EPS 1e-5f
#define SCAN_BLOCKS 49   // ceil(50000/1024)

typedef unsigned long long ull;

// ---------------- device scratch (no allocs allowed) ----------------
__device__ __align__(16) float g_h[N_NODES * DIM];
__device__ __align__(16) float g_agg[N_NODES * DIM];
__device__ int   g_deg[N_NODES];          // INVARIANT: zero on entry to kernel_launch
__device__ int   g_off[N_NODES + 1];
__device__ int   g_pos[N_NODES];
__device__ int   g_srcs[N_EDGES];
__device__ float g_inv[N_NODES];
__device__ int   g_done;
__device__ int   g_is32;

// ---------------- dtype detect + zero done counter ----------------
__global__ void k_detect(const unsigned int* __restrict__ w) {
    int i = blockIdx.x * blockDim.x + threadIdx.x;
    if (i == 0) g_done = 0;
    if (i < 2 * N_EDGES) {
        if ((i & 1) && w[i] != 0u) g_is32 = 1;  // idempotent
    }
}

__device__ __forceinline__ int load_idx(const void* ei, long long pos) {
    if (g_is32) return ((const int*)ei)[pos];
    return (int)((const long long*)ei)[pos];
}

// ---------------- count degrees (g_deg is zero by invariant) ----------------
__global__ void k_count(const void* __restrict__ ei) {
    int e = blockIdx.x * blockDim.x + threadIdx.x;
    if (e < N_EDGES) {
        int dst = load_idx(ei, (long long)N_EDGES + e);
        atomicAdd(&g_deg[dst], 1);
    }
}

// ---------------- scan + fill, one launch (49 co-resident blocks) ----------
__global__ void __launch_bounds__(1024) k_scan_fill(const void* __restrict__ ei) {
    __shared__ int ss[1024];
    __shared__ int sred[32];
    __shared__ int sbase;
    int b = blockIdx.x, t = threadIdx.x;
    int i = b * 1024 + t;

    // predecessor sum: sum g_deg[0 .. b*1024)
    int p = 0;
    for (int j = t; j < b * 1024; j += 1024) p += g_deg[j];
#pragma unroll
    for (int o = 16; o; o >>= 1) p += __shfl_xor_sync(0xffffffffu, p, o);
    if ((t & 31) == 0) sred[t >> 5] = p;
    __syncthreads();
    if (t < 32) {
        int s = sred[t];
#pragma unroll
        for (int o = 16; o; o >>= 1) s += __shfl_xor_sync(0xffffffffu, s, o);
        if (t == 0) sbase = s;
    }

    // intra-block inclusive scan of this block's degrees
    int d = (i < N_NODES) ? g_deg[i] : 0;
    ss[t] = d;
    __syncthreads();
#pragma unroll
    for (int off = 1; off < 1024; off <<= 1) {
        int v = (t >= off) ? ss[t - off] : 0;
        __syncthreads();
        ss[t] += v;
        __syncthreads();
    }
    int base = sbase;
    if (i < N_NODES) {
        int excl = ss[t] - d + base;
        g_off[i] = excl;
        g_pos[i] = excl;
        g_inv[i] = 1.0f / (float)max(d, 1);
    }
    if (b == SCAN_BLOCKS - 1 && t == 1023) g_off[N_NODES] = base + ss[1023];

    // grid barrier (all 49 blocks co-resident)
    __threadfence();
    __syncthreads();
    if (t == 0) {
        atomicAdd(&g_done, 1);
        while (*(volatile int*)&g_done < SCAN_BLOCKS) { }
    }
    __syncthreads();

    // fill phase + restore g_deg == 0 invariant
    for (int e = b * 1024 + t; e < N_EDGES; e += SCAN_BLOCKS * 1024) {
        int src = load_idx(ei, e);
        int dst = load_idx(ei, (long long)N_EDGES + e);
        int pp = atomicAdd(&g_pos[dst], 1);
        g_srcs[pp] = src;
    }
    for (int j = b * 1024 + t; j < N_NODES; j += SCAN_BLOCKS * 1024) g_deg[j] = 0;
}

// ---------------- mean-neighbor aggregation: warp per node ----------------
__global__ void k_aggregate(const float* __restrict__ hp) {
    int w = (blockIdx.x * blockDim.x + threadIdx.x) >> 5;
    if (w >= N_NODES) return;
    int lane = threadIdx.x & 31;
    int beg = g_off[w], end = g_off[w + 1];
    float4 acc = make_float4(0.f, 0.f, 0.f, 0.f);
    int e = beg;
    for (; e + 8 <= end; e += 8) {
        float4 v[8];
#pragma unroll
        for (int u = 0; u < 8; u++) {
            int s = g_srcs[e + u];
            v[u] = __ldg((const float4*)(hp + (long long)s * DIM + lane * 4));
        }
#pragma unroll
        for (int u = 0; u < 8; u++) {
            acc.x += v[u].x; acc.y += v[u].y; acc.z += v[u].z; acc.w += v[u].w;
        }
    }
    for (; e < end; e++) {
        int s = g_srcs[e];
        float4 v = __ldg((const float4*)(hp + (long long)s * DIM + lane * 4));
        acc.x += v.x; acc.y += v.y; acc.z += v.z; acc.w += v.w;
    }
    float inv = g_inv[w];
    acc.x *= inv; acc.y *= inv; acc.z *= inv; acc.w *= inv;
    *(float4*)(g_agg + (long long)w * DIM + lane * 4) = acc;
}

// ---------------- packed f32x2 + cp.async helpers ----------------
__device__ __forceinline__ ull fma2(ull a, ull b, ull c) {
    asm("fma.rn.f32x2 %0, %1, %2, %0;" : "+l"(c) : "l"(a), "l"(b));
    return c;
}
__device__ __forceinline__ float2 up2(ull v) {
    float2 r;
    asm("mov.b64 {%0, %1}, %2;" : "=f"(r.x), "=f"(r.y) : "l"(v));
    return r;
}
__device__ __forceinline__ void cp16(uint32_t s, const void* g) {
    asm volatile("cp.async.ca.shared.global [%0], [%1], 16;" :: "r"(s), "l"(g));
}
#define CP_COMMIT() asm volatile("cp.async.commit_group;")
#define CP_WAIT(n)  asm volatile("cp.async.wait_group %0;" :: "n"(n))

// ---------------- fused dual GEMM + bias + LayerNorm + ReLU ----------------
// h2 = agg@Wl^T + A2@Wr^T + b; dst = relu(LN(h2)).
// BM=128, BN=128, 512 threads. K streamed as 16 chunks of 16 (2 phases x 8),
// double-buffered via cp.async. Lane tx owns columns {tx, tx+32, tx+64, tx+96}
// -> all weight LDS.128 lane-contiguous (conflict-free); A loads are warp
// broadcasts. fma.rn.f32x2 with packed accumulators.
__global__ void __launch_bounds__(512)
k_gemm_ln(const float* __restrict__ A2, const float* __restrict__ Wl,
          const float* __restrict__ Wr, const float* __restrict__ bias,
          const float* __restrict__ gamma, const float* __restrict__ beta,
          float* __restrict__ dst) {
    __shared__ __align__(16) float sA[2][128 * 16];  // [m][k] within chunk
    __shared__ __align__(16) float sW[2][4 * 128 * 4]; // [kq][n] float4

    int tid = threadIdx.x;
    int ty = tid >> 5;   // warp 0..15 -> rows ty*8..ty*8+7
    int tx = tid & 31;   // lane -> cols tx+32j
    int m0 = blockIdx.x * 128;

    // per-thread load assignment
    int lm  = tid >> 2;        // 0..127 (row for A piece / n for W piece)
    int lkq = tid & 3;         // 0..3   (k-quad)
    bool a_ok = (m0 + lm) < N_NODES;

    uint32_t sA_s[2], sW_s[2];
    sA_s[0] = (uint32_t)__cvta_generic_to_shared(&sA[0][lm * 16 + lkq * 4]);
    sA_s[1] = (uint32_t)__cvta_generic_to_shared(&sA[1][lm * 16 + lkq * 4]);
    sW_s[0] = (uint32_t)__cvta_generic_to_shared(&sW[0][(lkq * 128 + lm) * 4]);
    sW_s[1] = (uint32_t)__cvta_generic_to_shared(&sW[1][(lkq * 128 + lm) * 4]);

    ull acc[8][4];
#pragma unroll
    for (int i = 0; i < 8; i++)
#pragma unroll
        for (int j = 0; j < 4; j++) acc[i][j] = 0ull;

    // chunk loader: ch in [0,16); phase 0 = (g_agg, Wl), phase 1 = (A2, Wr)
    auto load_chunk = [&](int buf, int ch) {
        const float* A = (ch < 8) ? g_agg : A2;
        const float* W = (ch < 8) ? Wl : Wr;
        int ko = (ch & 7) * 16;
        if (a_ok)
            cp16(sA_s[buf], A + (long long)(m0 + lm) * DIM + ko + lkq * 4);
        else
            *(float4*)&sA[buf][lm * 16 + lkq * 4] = make_float4(0.f, 0.f, 0.f, 0.f);
        cp16(sW_s[buf], W + lm * DIM + ko + lkq * 4);
    };

    load_chunk(0, 0);
    CP_COMMIT();

#pragma unroll 1
    for (int ch = 0; ch < 16; ch++) {
        int buf = ch & 1;
        if (ch < 15) {
            load_chunk(buf ^ 1, ch + 1);
            CP_COMMIT();
            CP_WAIT(1);
        } else {
            CP_WAIT(0);
        }
        __syncthreads();

        const float* cA = sA[buf];
        const float* cW = sW[buf];
#pragma unroll
        for (int kq = 0; kq < 4; kq++) {
            ulonglong2 b0 = *(const ulonglong2*)(cW + (kq * 128 + tx) * 4);
            ulonglong2 b1 = *(const ulonglong2*)(cW + (kq * 128 + tx + 32) * 4);
            ulonglong2 b2 = *(const ulonglong2*)(cW + (kq * 128 + tx + 64) * 4);
            ulonglong2 b3 = *(const ulonglong2*)(cW + (kq * 128 + tx + 96) * 4);
#pragma unroll
            for (int i = 0; i < 8; i++) {
                ulonglong2 av = *(const ulonglong2*)(cA + (ty * 8 + i) * 16 + kq * 4);
                acc[i][0] = fma2(av.x, b0.x, acc[i][0]);
                acc[i][0] = fma2(av.y, b0.y, acc[i][0]);
                acc[i][1] = fma2(av.x, b1.x, acc[i][1]);
                acc[i][1] = fma2(av.y, b1.y, acc[i][1]);
                acc[i][2] = fma2(av.x, b2.x, acc[i][2]);
                acc[i][2] = fma2(av.y, b2.y, acc[i][2]);
                acc[i][3] = fma2(av.x, b3.x, acc[i][3]);
                acc[i][3] = fma2(av.y, b3.y, acc[i][3]);
            }
        }
        __syncthreads();
    }

    // epilogue: horizontal add, +bias, LayerNorm across warp (full row), ReLU
    float bb[4], gg[4], be[4];
#pragma unroll
    for (int j = 0; j < 4; j++) {
        bb[j] = bias[tx + 32 * j];
        gg[j] = gamma[tx + 32 * j];
        be[j] = beta[tx + 32 * j];
    }
#pragma unroll
    for (int i = 0; i < 8; i++) {
        int m = m0 + ty * 8 + i;  // uniform across warp
        if (m >= N_NODES) continue;
        float dv[4];
#pragma unroll
        for (int j = 0; j < 4; j++) {
            float2 p = up2(acc[i][j]);
            dv[j] = p.x + p.y + bb[j];
        }
        float s = dv[0] + dv[1] + dv[2] + dv[3];
#pragma unroll
        for (int o = 16; o; o >>= 1) s += __shfl_xor_sync(0xffffffffu, s, o);
        float mu = s * (1.0f / 128.0f);
        float e0 = dv[0] - mu, e1 = dv[1] - mu, e2 = dv[2] - mu, e3 = dv[3] - mu;
        float q = e0 * e0 + e1 * e1 + e2 * e2 + e3 * e3;
#pragma unroll
        for (int o = 16; o; o >>= 1) q += __shfl_xor_sync(0xffffffffu, q, o);
        float rs = rsqrtf(q * (1.0f / 128.0f) + LN_EPS);
        float* row = dst + (long long)m * DIM;
        row[tx]      = fmaxf(e0 * rs * gg[0] + be[0], 0.f);
        row[tx + 32] = fmaxf(e1 * rs * gg[1] + be[1], 0.f);
        row[tx + 64] = fmaxf(e2 * rs * gg[2] + be[2], 0.f);
        row[tx + 96] = fmaxf(e3 * rs * gg[3] + be[3], 0.f);
    }
}

// ---------------- launch ----------------
extern "C" void kernel_launch(void* const* d_in, const int* in_sizes, int n_in,
                              void* d_out, int out_size) {
    const float* x     = (const float*)d_in[0];
    const void*  ei    = d_in[1];
    const float* Wl    = (const float*)d_in[2];
    const float* bl    = (const float*)d_in[3];
    const float* Wr    = (const float*)d_in[4];
    const float* gamma = (const float*)d_in[5];
    const float* beta  = (const float*)d_in[6];
    float* out = (float*)d_out;

    static float* hdev = nullptr;
    if (!hdev) cudaGetSymbolAddress((void**)&hdev, g_h);

    k_detect<<<(2 * N_EDGES + 255) / 256, 256>>>((const unsigned int*)ei);
    k_count<<<(N_EDGES + 255) / 256, 256>>>(ei);
    k_scan_fill<<<SCAN_BLOCKS, 1024>>>(ei);

    for (int l = 0; l < NLAYERS; l++) {
        const float* hsrc = (l == 0) ? x : hdev;
        float* dst = (l == NLAYERS - 1) ? out : hdev;
        k_aggregate<<<(N_NODES + 7) / 8, 256>>>(hsrc);
        k_gemm_ln<<<(N_NODES + 127) / 128, 512>>>(
            hsrc, Wl + l * DIM * DIM, Wr + l * DIM * DIM, bl + l * DIM,
            gamma + l * DIM, beta + l * DIM, dst);
    }
}

// round 7
// speedup vs baseline: 1.8709x; 1.5288x over previous
#include <cuda_runtime.h>
#include <cuda_bf16.h>
#include <cstdint>

#define N_NODES 50000
#define N_EDGES 800000
#define DIM 128
#define NLAYERS 3
#define LN_EPS 1e-5f
#define SCAN_BLOCKS 49
#define AS 72   // smem tile stride in bf16 (64 + 8 pad, conflict-free)

typedef unsigned long long ull;

// ---------------- device scratch ----------------
__device__ __align__(16) float g_h[N_NODES * DIM];
__device__ __align__(16) __nv_bfloat16 g_abhi[N_NODES * DIM];
__device__ __align__(16) __nv_bfloat16 g_ablo[N_NODES * DIM];
__device__ __align__(16) __nv_bfloat16 g_hbhi[N_NODES * DIM];
__device__ __align__(16) __nv_bfloat16 g_hblo[N_NODES * DIM];
__device__ __align__(16) __nv_bfloat16 g_wbhi[NLAYERS * DIM * 2 * DIM]; // [l][n][k 0..255]
__device__ __align__(16) __nv_bfloat16 g_wblo[NLAYERS * DIM * 2 * DIM];
__device__ int   g_deg[N_NODES];   // INVARIANT: zero on entry
__device__ int   g_off[N_NODES + 1];
__device__ int   g_pos[N_NODES];
__device__ int   g_srcs[N_EDGES];
__device__ float g_inv[N_NODES];
__device__ int   g_done;
__device__ int   g_is32;

__device__ __forceinline__ void split_bf16(float v, __nv_bfloat16& hi, __nv_bfloat16& lo) {
    hi = __float2bfloat16(v);
    lo = __float2bfloat16(v - __bfloat162float(hi));
}

// ---------------- dtype detect + zero done counter ----------------
__global__ void k_detect(const unsigned int* __restrict__ w) {
    int i = blockIdx.x * blockDim.x + threadIdx.x;
    if (i == 0) g_done = 0;
    if (i < 2 * N_EDGES) {
        if ((i & 1) && w[i] != 0u) g_is32 = 1;
    }
}

__device__ __forceinline__ int load_idx(const void* ei, long long pos) {
    if (g_is32) return ((const int*)ei)[pos];
    return (int)((const long long*)ei)[pos];
}

__global__ void k_count(const void* __restrict__ ei) {
    int e = blockIdx.x * blockDim.x + threadIdx.x;
    if (e < N_EDGES) atomicAdd(&g_deg[load_idx(ei, (long long)N_EDGES + e)], 1);
}

// ---------------- scan + fill (49 co-resident blocks) ----------------
__global__ void __launch_bounds__(1024) k_scan_fill(const void* __restrict__ ei) {
    __shared__ int ss[1024];
    __shared__ int sred[32];
    __shared__ int sbase;
    int b = blockIdx.x, t = threadIdx.x;
    int i = b * 1024 + t;

    int p = 0;
    for (int j = t; j < b * 1024; j += 1024) p += g_deg[j];
#pragma unroll
    for (int o = 16; o; o >>= 1) p += __shfl_xor_sync(0xffffffffu, p, o);
    if ((t & 31) == 0) sred[t >> 5] = p;
    __syncthreads();
    if (t < 32) {
        int s = sred[t];
#pragma unroll
        for (int o = 16; o; o >>= 1) s += __shfl_xor_sync(0xffffffffu, s, o);
        if (t == 0) sbase = s;
    }
    int d = (i < N_NODES) ? g_deg[i] : 0;
    ss[t] = d;
    __syncthreads();
#pragma unroll
    for (int off = 1; off < 1024; off <<= 1) {
        int v = (t >= off) ? ss[t - off] : 0;
        __syncthreads();
        ss[t] += v;
        __syncthreads();
    }
    int base = sbase;
    if (i < N_NODES) {
        int excl = ss[t] - d + base;
        g_off[i] = excl;
        g_pos[i] = excl;
        g_inv[i] = 1.0f / (float)max(d, 1);
    }
    if (b == SCAN_BLOCKS - 1 && t == 1023) g_off[N_NODES] = base + ss[1023];

    __threadfence();
    __syncthreads();
    if (t == 0) {
        atomicAdd(&g_done, 1);
        while (*(volatile int*)&g_done < SCAN_BLOCKS) { }
    }
    __syncthreads();

    for (int e = b * 1024 + t; e < N_EDGES; e += SCAN_BLOCKS * 1024) {
        int src = load_idx(ei, e);
        int dst = load_idx(ei, (long long)N_EDGES + e);
        int pp = atomicAdd(&g_pos[dst], 1);
        g_srcs[pp] = src;
    }
    for (int j = b * 1024 + t; j < N_NODES; j += SCAN_BLOCKS * 1024) g_deg[j] = 0;
}

// ---------------- split x -> h hi/lo (layer-0 self term) ----------------
__global__ void k_convx(const float* __restrict__ x) {
    int i = blockIdx.x * blockDim.x + threadIdx.x;
    if (i < N_NODES * DIM) {
        __nv_bfloat16 hi, lo;
        split_bf16(x[i], hi, lo);
        g_hbhi[i] = hi;
        g_hblo[i] = lo;
    }
}

// ---------------- split weights: [l][n][k], k<128 -> Wl, else Wr ------------
__global__ void k_convw(const float* __restrict__ Wl, const float* __restrict__ Wr) {
    int idx = blockIdx.x * blockDim.x + threadIdx.x;
    if (idx >= NLAYERS * DIM * 2 * DIM) return;
    int l = idx / (DIM * 2 * DIM);
    int r = idx % (DIM * 2 * DIM);
    int n = r / (2 * DIM);
    int k = r % (2 * DIM);
    float v = (k < DIM) ? Wl[l * DIM * DIM + n * DIM + k]
                        : Wr[l * DIM * DIM + n * DIM + (k - DIM)];
    __nv_bfloat16 hi, lo;
    split_bf16(v, hi, lo);
    g_wbhi[idx] = hi;
    g_wblo[idx] = lo;
}

// ---------------- mean aggregation: warp per node, emits bf16 hi/lo --------
__global__ void k_aggregate(const float* __restrict__ hp) {
    int w = (blockIdx.x * blockDim.x + threadIdx.x) >> 5;
    if (w >= N_NODES) return;
    int lane = threadIdx.x & 31;
    int beg = g_off[w], end = g_off[w + 1];
    float4 acc = make_float4(0.f, 0.f, 0.f, 0.f);
    int e = beg;
    for (; e + 8 <= end; e += 8) {
        float4 v[8];
#pragma unroll
        for (int u = 0; u < 8; u++) {
            int s = g_srcs[e + u];
            v[u] = __ldg((const float4*)(hp + (long long)s * DIM + lane * 4));
        }
#pragma unroll
        for (int u = 0; u < 8; u++) {
            acc.x += v[u].x; acc.y += v[u].y; acc.z += v[u].z; acc.w += v[u].w;
        }
    }
    for (; e < end; e++) {
        int s = g_srcs[e];
        float4 v = __ldg((const float4*)(hp + (long long)s * DIM + lane * 4));
        acc.x += v.x; acc.y += v.y; acc.z += v.z; acc.w += v.w;
    }
    float inv = g_inv[w];
    float vals[4] = {acc.x * inv, acc.y * inv, acc.z * inv, acc.w * inv};
    __nv_bfloat16 hi[4], lo[4];
#pragma unroll
    for (int j = 0; j < 4; j++) split_bf16(vals[j], hi[j], lo[j]);
    long long o = (long long)w * DIM + lane * 4;
    *(__nv_bfloat162*)(g_abhi + o)     = __nv_bfloat162(hi[0], hi[1]);
    *(__nv_bfloat162*)(g_abhi + o + 2) = __nv_bfloat162(hi[2], hi[3]);
    *(__nv_bfloat162*)(g_ablo + o)     = __nv_bfloat162(lo[0], lo[1]);
    *(__nv_bfloat162*)(g_ablo + o + 2) = __nv_bfloat162(lo[2], lo[3]);
}

// ---------------- HMMA m16n8k16 bf16 ----------------
__device__ __forceinline__ void mma16816(float* c, const uint32_t* a, const uint32_t* b) {
    asm volatile(
        "mma.sync.aligned.m16n8k16.row.col.f32.bf16.bf16.f32 "
        "{%0,%1,%2,%3}, {%4,%5,%6,%7}, {%8,%9}, {%0,%1,%2,%3};"
        : "+f"(c[0]), "+f"(c[1]), "+f"(c[2]), "+f"(c[3])
        : "r"(a[0]), "r"(a[1]), "r"(a[2]), "r"(a[3]), "r"(b[0]), "r"(b[1]));
}

// ---------------- fused dual GEMM (HMMA) + bias + LN + ReLU ----------------
// D[128 x 128] = sum of 3 passes (Ahi.Bhi, Ahi.Blo, Alo.Bhi), K=256 per pass,
// streamed as 12 chunks of 64 with register prefetch. 8 warps: warp tile 64x32.
__global__ void __launch_bounds__(256)
k_gemm_ln(int lw, const float* __restrict__ bias, const float* __restrict__ gamma,
          const float* __restrict__ beta, float* __restrict__ dstF, int write_bf16) {
    __shared__ __align__(16) __nv_bfloat16 sA[128 * AS];  // 18432 B
    __shared__ __align__(16) __nv_bfloat16 sB[128 * AS];  // 18432 B
    __shared__ float s_sum[128], s_sq[128];
    __shared__ float s_bias[128], s_gamma[128], s_beta[128];

    int tid = threadIdx.x;
    int wid = tid >> 5;
    int lane = tid & 31;
    int gid = lane >> 2;   // group (row within 8)
    int qid = lane & 3;    // thread-in-group (k/col pair)
    int wm = wid & 1;      // M half: rows wm*64..wm*64+63
    int wn = wid >> 1;     // N quarter: cols wn*32..wn*32+31
    int m0 = blockIdx.x * 128;

    if (tid < 128) {
        s_bias[tid] = bias[tid];
        s_gamma[tid] = gamma[tid];
        s_beta[tid] = beta[tid];
        s_sum[tid] = 0.f;
        s_sq[tid] = 0.f;
    }

    // tile-copy assignment: 4 pieces per thread, piece j covers row u>>3, 8 bf16
    int crow[4], cuc[4];
#pragma unroll
    for (int j = 0; j < 4; j++) {
        int u = tid + 256 * j;
        crow[j] = u >> 3;
        cuc[j] = u & 7;
    }

    const __nv_bfloat16* wb_hi = g_wbhi + (long long)lw * DIM * 2 * DIM;
    const __nv_bfloat16* wb_lo = g_wblo + (long long)lw * DIM * 2 * DIM;

    float acc[4][4][4];
#pragma unroll
    for (int mf = 0; mf < 4; mf++)
#pragma unroll
        for (int nf = 0; nf < 4; nf++)
#pragma unroll
            for (int j = 0; j < 4; j++) acc[mf][nf][j] = 0.f;

    uint4 va[4], vb[4];
    // chunk it: pass p = it>>2, c = it&3. A: c<2 -> agg cols c*64; else h cols (c-2)*64.
    auto load_regs = [&](int it) {
        int p = it >> 2;
        int c = it & 3;
        const __nv_bfloat16* Asrc;
        int acol;
        if (c < 2) { Asrc = (p < 2) ? g_abhi : g_ablo; acol = c * 64; }
        else       { Asrc = (p < 2) ? g_hbhi : g_hblo; acol = (c - 2) * 64; }
        const __nv_bfloat16* Bsrc = (p == 1) ? wb_lo : wb_hi;
        int bcol = c * 64;
#pragma unroll
        for (int j = 0; j < 4; j++) {
            int row = crow[j], uc = cuc[j];
            va[j] = make_uint4(0, 0, 0, 0);
            if (m0 + row < N_NODES)
                va[j] = *(const uint4*)(Asrc + (long long)(m0 + row) * DIM + acol + uc * 8);
            vb[j] = *(const uint4*)(Bsrc + (long long)row * 256 + bcol + uc * 8);
        }
    };

    load_regs(0);

#pragma unroll 1
    for (int it = 0; it < 12; it++) {
        __syncthreads();   // previous compute done reading smem
#pragma unroll
        for (int j = 0; j < 4; j++) {
            *(uint4*)(sA + crow[j] * AS + cuc[j] * 8) = va[j];
            *(uint4*)(sB + crow[j] * AS + cuc[j] * 8) = vb[j];
        }
        __syncthreads();
        if (it < 11) load_regs(it + 1);   // prefetch under compute

#pragma unroll
        for (int ks = 0; ks < 4; ks++) {
            uint32_t ar[4][4];
#pragma unroll
            for (int mf = 0; mf < 4; mf++) {
                int r0 = wm * 64 + mf * 16 + gid;
                int k0 = ks * 16 + qid * 2;
                ar[mf][0] = *(const uint32_t*)(sA + r0 * AS + k0);
                ar[mf][1] = *(const uint32_t*)(sA + (r0 + 8) * AS + k0);
                ar[mf][2] = *(const uint32_t*)(sA + r0 * AS + k0 + 8);
                ar[mf][3] = *(const uint32_t*)(sA + (r0 + 8) * AS + k0 + 8);
            }
            uint32_t br[4][2];
#pragma unroll
            for (int nf = 0; nf < 4; nf++) {
                int n0 = wn * 32 + nf * 8 + gid;
                int k0 = ks * 16 + qid * 2;
                br[nf][0] = *(const uint32_t*)(sB + n0 * AS + k0);
                br[nf][1] = *(const uint32_t*)(sB + n0 * AS + k0 + 8);
            }
#pragma unroll
            for (int mf = 0; mf < 4; mf++)
#pragma unroll
                for (int nf = 0; nf < 4; nf++)
                    mma16816(acc[mf][nf], ar[mf], br[nf]);
        }
    }
    __syncthreads();

    // ---- LN stats: per-row partial sums over this warp's 32 cols ----
#pragma unroll
    for (int mf = 0; mf < 4; mf++) {
#pragma unroll
        for (int h = 0; h < 2; h++) {
            float ps = 0.f, pq = 0.f;
#pragma unroll
            for (int nf = 0; nf < 4; nf++) {
#pragma unroll
                for (int j = 0; j < 2; j++) {
                    int col = wn * 32 + nf * 8 + qid * 2 + j;
                    float f = acc[mf][nf][h * 2 + j] + s_bias[col];
                    acc[mf][nf][h * 2 + j] = f;   // keep biased value
                    ps += f;
                    pq += f * f;
                }
            }
            // reduce across the 4 lanes sharing this row
            ps += __shfl_xor_sync(0xffffffffu, ps, 1);
            pq += __shfl_xor_sync(0xffffffffu, pq, 1);
            ps += __shfl_xor_sync(0xffffffffu, ps, 2);
            pq += __shfl_xor_sync(0xffffffffu, pq, 2);
            if (qid == 0) {
                int rl = wm * 64 + mf * 16 + h * 8 + gid;
                atomicAdd(&s_sum[rl], ps);
                atomicAdd(&s_sq[rl], pq);
            }
        }
    }
    __syncthreads();

    // ---- normalize + ReLU + write ----
#pragma unroll
    for (int mf = 0; mf < 4; mf++) {
#pragma unroll
        for (int h = 0; h < 2; h++) {
            int rl = wm * 64 + mf * 16 + h * 8 + gid;
            int m = m0 + rl;
            if (m >= N_NODES) continue;
            float mu = s_sum[rl] * (1.0f / 128.0f);
            float var = s_sq[rl] * (1.0f / 128.0f) - mu * mu;
            float rs = rsqrtf(var + LN_EPS);
            long long ro = (long long)m * DIM;
#pragma unroll
            for (int nf = 0; nf < 4; nf++) {
                int col = wn * 32 + nf * 8 + qid * 2;
                float f0 = acc[mf][nf][h * 2];
                float f1 = acc[mf][nf][h * 2 + 1];
                float o0 = fmaxf((f0 - mu) * rs * s_gamma[col] + s_beta[col], 0.f);
                float o1 = fmaxf((f1 - mu) * rs * s_gamma[col + 1] + s_beta[col + 1], 0.f);
                *(float2*)(dstF + ro + col) = make_float2(o0, o1);
                if (write_bf16) {
                    __nv_bfloat16 h0, l0, h1, l1;
                    split_bf16(o0, h0, l0);
                    split_bf16(o1, h1, l1);
                    *(__nv_bfloat162*)(g_hbhi + ro + col) = __nv_bfloat162(h0, h1);
                    *(__nv_bfloat162*)(g_hblo + ro + col) = __nv_bfloat162(l0, l1);
                }
            }
        }
    }
}

// ---------------- launch ----------------
extern "C" void kernel_launch(void* const* d_in, const int* in_sizes, int n_in,
                              void* d_out, int out_size) {
    const float* x     = (const float*)d_in[0];
    const void*  ei    = d_in[1];
    const float* Wl    = (const float*)d_in[2];
    const float* bl    = (const float*)d_in[3];
    const float* Wr    = (const float*)d_in[4];
    const float* gamma = (const float*)d_in[5];
    const float* beta  = (const float*)d_in[6];
    float* out = (float*)d_out;

    static float* hdev = nullptr;
    if (!hdev) cudaGetSymbolAddress((void**)&hdev, g_h);

    k_detect<<<(2 * N_EDGES + 255) / 256, 256>>>((const unsigned int*)ei);
    k_count<<<(N_EDGES + 255) / 256, 256>>>(ei);
    k_scan_fill<<<SCAN_BLOCKS, 1024>>>(ei);
    k_convx<<<(N_NODES * DIM + 255) / 256, 256>>>(x);
    k_convw<<<(NLAYERS * DIM * 2 * DIM + 255) / 256, 256>>>(Wl, Wr);

    for (int l = 0; l < NLAYERS; l++) {
        const float* hsrc = (l == 0) ? x : hdev;
        float* dstF = (l == NLAYERS - 1) ? out : hdev;
        int wbf = (l == NLAYERS - 1) ? 0 : 1;
        k_aggregate<<<(N_NODES + 7) / 8, 256>>>(hsrc);
        k_gemm_ln<<<(N_NODES + 127) / 128, 256>>>(
            l, bl + l * DIM, gamma + l * DIM, beta + l * DIM, dstF, wbf);
    }
}

// round 8
// speedup vs baseline: 2.0412x; 1.0910x over previous
#include <cuda_runtime.h>
#include <cuda_bf16.h>
#include <cstdint>

#define N_NODES 50000
#define N_EDGES 800000
#define DIM 128
#define NLAYERS 3
#define LN_EPS 1e-5f
#define SCAN_BLOCKS 49
#define AS 72   // smem tile stride in bf16 (144B: rows land on distinct banks)

typedef unsigned long long ull;

// ---------------- device scratch ----------------
__device__ __align__(16) float g_h[N_NODES * DIM];
__device__ __align__(16) __nv_bfloat16 g_abhi[N_NODES * DIM];
__device__ __align__(16) __nv_bfloat16 g_ablo[N_NODES * DIM];
__device__ __align__(16) __nv_bfloat16 g_hbhi[N_NODES * DIM];
__device__ __align__(16) __nv_bfloat16 g_hblo[N_NODES * DIM];
__device__ __align__(16) __nv_bfloat16 g_wbhi[NLAYERS * DIM * 2 * DIM];
__device__ __align__(16) __nv_bfloat16 g_wblo[NLAYERS * DIM * 2 * DIM];
__device__ int   g_deg[N_NODES];   // INVARIANT: zero on entry
__device__ int   g_off[N_NODES + 1];
__device__ int   g_pos[N_NODES];
__device__ int   g_srcs[N_EDGES];
__device__ float g_inv[N_NODES];
__device__ int   g_done;
__device__ int   g_is32;

__device__ __forceinline__ void split_bf16(float v, __nv_bfloat16& hi, __nv_bfloat16& lo) {
    hi = __float2bfloat16(v);
    lo = __float2bfloat16(v - __bfloat162float(hi));
}

// ---------------- dtype detect (vectorized) + zero done counter ----------------
__global__ void k_detect(const uint4* __restrict__ w) {
    int i = blockIdx.x * blockDim.x + threadIdx.x;   // over 2*N_EDGES/4 uint4
    if (i == 0) g_done = 0;
    if (i < (2 * N_EDGES) / 4) {
        uint4 v = w[i];
        if (v.y | v.w) g_is32 = 1;   // odd words nonzero => int32 layout
    }
}

__device__ __forceinline__ int load_idx(const void* ei, long long pos) {
    if (g_is32) return ((const int*)ei)[pos];
    return (int)((const long long*)ei)[pos];
}

__global__ void k_count(const void* __restrict__ ei) {
    int e = blockIdx.x * blockDim.x + threadIdx.x;
    if (e < N_EDGES) atomicAdd(&g_deg[load_idx(ei, (long long)N_EDGES + e)], 1);
}

// ---------------- scan + fill (49 co-resident blocks) ----------------
__global__ void __launch_bounds__(1024) k_scan_fill(const void* __restrict__ ei) {
    __shared__ int ss[1024];
    __shared__ int sred[32];
    __shared__ int sbase;
    int b = blockIdx.x, t = threadIdx.x;
    int i = b * 1024 + t;

    int p = 0;
    for (int j = t; j < b * 1024; j += 1024) p += g_deg[j];
#pragma unroll
    for (int o = 16; o; o >>= 1) p += __shfl_xor_sync(0xffffffffu, p, o);
    if ((t & 31) == 0) sred[t >> 5] = p;
    __syncthreads();
    if (t < 32) {
        int s = sred[t];
#pragma unroll
        for (int o = 16; o; o >>= 1) s += __shfl_xor_sync(0xffffffffu, s, o);
        if (t == 0) sbase = s;
    }
    int d = (i < N_NODES) ? g_deg[i] : 0;
    ss[t] = d;
    __syncthreads();
#pragma unroll
    for (int off = 1; off < 1024; off <<= 1) {
        int v = (t >= off) ? ss[t - off] : 0;
        __syncthreads();
        ss[t] += v;
        __syncthreads();
    }
    int base = sbase;
    if (i < N_NODES) {
        int excl = ss[t] - d + base;
        g_off[i] = excl;
        g_pos[i] = excl;
        g_inv[i] = 1.0f / (float)max(d, 1);
    }
    if (b == SCAN_BLOCKS - 1 && t == 1023) g_off[N_NODES] = base + ss[1023];

    __threadfence();
    __syncthreads();
    if (t == 0) {
        atomicAdd(&g_done, 1);
        while (*(volatile int*)&g_done < SCAN_BLOCKS) { }
    }
    __syncthreads();

    for (int e = b * 1024 + t; e < N_EDGES; e += SCAN_BLOCKS * 1024) {
        int src = load_idx(ei, e);
        int dst = load_idx(ei, (long long)N_EDGES + e);
        int pp = atomicAdd(&g_pos[dst], 1);
        g_srcs[pp] = src;
    }
    for (int j = b * 1024 + t; j < N_NODES; j += SCAN_BLOCKS * 1024) g_deg[j] = 0;
}

// ---------------- split x -> h hi/lo, vectorized (4 floats/thread) ----------
__global__ void k_convx(const float4* __restrict__ x) {
    int i = blockIdx.x * blockDim.x + threadIdx.x;
    if (i < (N_NODES * DIM) / 4) {
        float4 v = x[i];
        __nv_bfloat16 h0, l0, h1, l1, h2, l2, h3, l3;
        split_bf16(v.x, h0, l0);
        split_bf16(v.y, h1, l1);
        split_bf16(v.z, h2, l2);
        split_bf16(v.w, h3, l3);
        *(__nv_bfloat162*)(g_hbhi + i * 4)     = __nv_bfloat162(h0, h1);
        *(__nv_bfloat162*)(g_hbhi + i * 4 + 2) = __nv_bfloat162(h2, h3);
        *(__nv_bfloat162*)(g_hblo + i * 4)     = __nv_bfloat162(l0, l1);
        *(__nv_bfloat162*)(g_hblo + i * 4 + 2) = __nv_bfloat162(l2, l3);
    }
}

// ---------------- split weights: [l][n][k], k<128 -> Wl, else Wr ------------
__global__ void k_convw(const float* __restrict__ Wl, const float* __restrict__ Wr) {
    int idx = blockIdx.x * blockDim.x + threadIdx.x;
    if (idx >= NLAYERS * DIM * 2 * DIM) return;
    int l = idx / (DIM * 2 * DIM);
    int r = idx % (DIM * 2 * DIM);
    int n = r / (2 * DIM);
    int k = r % (2 * DIM);
    float v = (k < DIM) ? Wl[l * DIM * DIM + n * DIM + k]
                        : Wr[l * DIM * DIM + n * DIM + (k - DIM)];
    __nv_bfloat16 hi, lo;
    split_bf16(v, hi, lo);
    g_wbhi[idx] = hi;
    g_wblo[idx] = lo;
}

// ---------------- mean aggregation: warp per node, emits bf16 hi/lo --------
__global__ void k_aggregate(const float* __restrict__ hp) {
    int w = (blockIdx.x * blockDim.x + threadIdx.x) >> 5;
    if (w >= N_NODES) return;
    int lane = threadIdx.x & 31;
    int beg = g_off[w], end = g_off[w + 1];
    float4 acc = make_float4(0.f, 0.f, 0.f, 0.f);
    int e = beg;
    for (; e + 8 <= end; e += 8) {
        float4 v[8];
#pragma unroll
        for (int u = 0; u < 8; u++) {
            int s = g_srcs[e + u];
            v[u] = __ldg((const float4*)(hp + (long long)s * DIM + lane * 4));
        }
#pragma unroll
        for (int u = 0; u < 8; u++) {
            acc.x += v[u].x; acc.y += v[u].y; acc.z += v[u].z; acc.w += v[u].w;
        }
    }
    for (; e < end; e++) {
        int s = g_srcs[e];
        float4 v = __ldg((const float4*)(hp + (long long)s * DIM + lane * 4));
        acc.x += v.x; acc.y += v.y; acc.z += v.z; acc.w += v.w;
    }
    float inv = g_inv[w];
    float vals[4] = {acc.x * inv, acc.y * inv, acc.z * inv, acc.w * inv};
    __nv_bfloat16 hi[4], lo[4];
#pragma unroll
    for (int j = 0; j < 4; j++) split_bf16(vals[j], hi[j], lo[j]);
    long long o = (long long)w * DIM + lane * 4;
    *(__nv_bfloat162*)(g_abhi + o)     = __nv_bfloat162(hi[0], hi[1]);
    *(__nv_bfloat162*)(g_abhi + o + 2) = __nv_bfloat162(hi[2], hi[3]);
    *(__nv_bfloat162*)(g_ablo + o)     = __nv_bfloat162(lo[0], lo[1]);
    *(__nv_bfloat162*)(g_ablo + o + 2) = __nv_bfloat162(lo[2], lo[3]);
}

// ---------------- HMMA m16n8k16 bf16 + ldmatrix ----------------
__device__ __forceinline__ void mma16816(float* c, const uint32_t* a, const uint32_t* b) {
    asm volatile(
        "mma.sync.aligned.m16n8k16.row.col.f32.bf16.bf16.f32 "
        "{%0,%1,%2,%3}, {%4,%5,%6,%7}, {%8,%9}, {%0,%1,%2,%3};"
        : "+f"(c[0]), "+f"(c[1]), "+f"(c[2]), "+f"(c[3])
        : "r"(a[0]), "r"(a[1]), "r"(a[2]), "r"(a[3]), "r"(b[0]), "r"(b[1]));
}
__device__ __forceinline__ void ldsm4(uint32_t* r, uint32_t addr) {
    asm volatile("ldmatrix.sync.aligned.m8n8.x4.shared.b16 {%0,%1,%2,%3}, [%4];"
                 : "=r"(r[0]), "=r"(r[1]), "=r"(r[2]), "=r"(r[3]) : "r"(addr));
}

// ---------------- fused dual GEMM (HMMA+LDSM) + bias + LN + ReLU -----------
__global__ void __launch_bounds__(256)
k_gemm_ln(int lw, const float* __restrict__ bias, const float* __restrict__ gamma,
          const float* __restrict__ beta, float* __restrict__ dstF, int write_bf16) {
    __shared__ __align__(16) __nv_bfloat16 sA[128 * AS];
    __shared__ __align__(16) __nv_bfloat16 sB[128 * AS];
    __shared__ float s_sum[128], s_sq[128];
    __shared__ float s_bias[128], s_gamma[128], s_beta[128];

    int tid = threadIdx.x;
    int wid = tid >> 5;
    int lane = tid & 31;
    int gid = lane >> 2;
    int qid = lane & 3;
    int wm = wid & 1;      // M half
    int wn = wid >> 1;     // N quarter
    int m0 = blockIdx.x * 128;

    if (tid < 128) {
        s_bias[tid] = bias[tid];
        s_gamma[tid] = gamma[tid];
        s_beta[tid] = beta[tid];
        s_sum[tid] = 0.f;
        s_sq[tid] = 0.f;
    }

    // ldmatrix lane->address maps (element offsets into the tile)
    // A (per mf): row = wm*64 + mf*16 + (lane&15), k = ks*16 + (lane>>4)*8
    uint32_t sA_u = (uint32_t)__cvta_generic_to_shared(sA);
    uint32_t sB_u = (uint32_t)__cvta_generic_to_shared(sB);
    uint32_t a_addr0 = sA_u + ((wm * 64 + (lane & 15)) * AS + (lane >> 4) * 8) * 2;
    // B (per nf pair): row = wn*32 + pair*16 + (lane&7) + (lane>>4)*8,
    //                  k = ks*16 + ((lane>>3)&1)*8
    uint32_t b_addr0 = sB_u + ((wn * 32 + (lane & 7) + (lane >> 4) * 8) * AS
                               + ((lane >> 3) & 1) * 8) * 2;

    int crow[4], cuc[4];
#pragma unroll
    for (int j = 0; j < 4; j++) {
        int u = tid + 256 * j;
        crow[j] = u >> 3;
        cuc[j] = u & 7;
    }

    const __nv_bfloat16* wb_hi = g_wbhi + (long long)lw * DIM * 2 * DIM;
    const __nv_bfloat16* wb_lo = g_wblo + (long long)lw * DIM * 2 * DIM;

    float acc[4][4][4];
#pragma unroll
    for (int mf = 0; mf < 4; mf++)
#pragma unroll
        for (int nf = 0; nf < 4; nf++)
#pragma unroll
            for (int j = 0; j < 4; j++) acc[mf][nf][j] = 0.f;

    uint4 va[4], vb[4];
    auto load_regs = [&](int it) {
        int p = it >> 2;
        int c = it & 3;
        const __nv_bfloat16* Asrc;
        int acol;
        if (c < 2) { Asrc = (p < 2) ? g_abhi : g_ablo; acol = c * 64; }
        else       { Asrc = (p < 2) ? g_hbhi : g_hblo; acol = (c - 2) * 64; }
        const __nv_bfloat16* Bsrc = (p == 1) ? wb_lo : wb_hi;
        int bcol = c * 64;
#pragma unroll
        for (int j = 0; j < 4; j++) {
            int row = crow[j], uc = cuc[j];
            va[j] = make_uint4(0, 0, 0, 0);
            if (m0 + row < N_NODES)
                va[j] = *(const uint4*)(Asrc + (long long)(m0 + row) * DIM + acol + uc * 8);
            vb[j] = *(const uint4*)(Bsrc + (long long)row * 256 + bcol + uc * 8);
        }
    };

    load_regs(0);

#pragma unroll 1
    for (int it = 0; it < 12; it++) {
        __syncthreads();
#pragma unroll
        for (int j = 0; j < 4; j++) {
            *(uint4*)(sA + crow[j] * AS + cuc[j] * 8) = va[j];
            *(uint4*)(sB + crow[j] * AS + cuc[j] * 8) = vb[j];
        }
        __syncthreads();
        if (it < 11) load_regs(it + 1);

#pragma unroll
        for (int ks = 0; ks < 4; ks++) {
            uint32_t ar[4][4];
#pragma unroll
            for (int mf = 0; mf < 4; mf++)
                ldsm4(ar[mf], a_addr0 + (mf * 16 * AS + ks * 16) * 2);
            uint32_t br[2][4];  // [pair][4 regs] = nf(2*pair){b0,b1}, nf(2*pair+1){b0,b1}
#pragma unroll
            for (int pr = 0; pr < 2; pr++)
                ldsm4(br[pr], b_addr0 + (pr * 16 * AS + ks * 16) * 2);
#pragma unroll
            for (int mf = 0; mf < 4; mf++)
#pragma unroll
                for (int nf = 0; nf < 4; nf++)
                    mma16816(acc[mf][nf], ar[mf], &br[nf >> 1][(nf & 1) * 2]);
        }
    }
    __syncthreads();

    // ---- LN stats ----
#pragma unroll
    for (int mf = 0; mf < 4; mf++) {
#pragma unroll
        for (int h = 0; h < 2; h++) {
            float ps = 0.f, pq = 0.f;
#pragma unroll
            for (int nf = 0; nf < 4; nf++) {
#pragma unroll
                for (int j = 0; j < 2; j++) {
                    int col = wn * 32 + nf * 8 + qid * 2 + j;
                    float f = acc[mf][nf][h * 2 + j] + s_bias[col];
                    acc[mf][nf][h * 2 + j] = f;
                    ps += f;
                    pq += f * f;
                }
            }
            ps += __shfl_xor_sync(0xffffffffu, ps, 1);
            pq += __shfl_xor_sync(0xffffffffu, pq, 1);
            ps += __shfl_xor_sync(0xffffffffu, ps, 2);
            pq += __shfl_xor_sync(0xffffffffu, pq, 2);
            if (qid == 0) {
                int rl = wm * 64 + mf * 16 + h * 8 + gid;
                atomicAdd(&s_sum[rl], ps);
                atomicAdd(&s_sq[rl], pq);
            }
        }
    }
    __syncthreads();

    // ---- normalize + ReLU + write ----
#pragma unroll
    for (int mf = 0; mf < 4; mf++) {
#pragma unroll
        for (int h = 0; h < 2; h++) {
            int rl = wm * 64 + mf * 16 + h * 8 + gid;
            int m = m0 + rl;
            if (m >= N_NODES) continue;
            float mu = s_sum[rl] * (1.0f / 128.0f);
            float var = s_sq[rl] * (1.0f / 128.0f) - mu * mu;
            float rs = rsqrtf(var + LN_EPS);
            long long ro = (long long)m * DIM;
#pragma unroll
            for (int nf = 0; nf < 4; nf++) {
                int col = wn * 32 + nf * 8 + qid * 2;
                float f0 = acc[mf][nf][h * 2];
                float f1 = acc[mf][nf][h * 2 + 1];
                float o0 = fmaxf((f0 - mu) * rs * s_gamma[col] + s_beta[col], 0.f);
                float o1 = fmaxf((f1 - mu) * rs * s_gamma[col + 1] + s_beta[col + 1], 0.f);
                *(float2*)(dstF + ro + col) = make_float2(o0, o1);
                if (write_bf16) {
                    __nv_bfloat16 h0, l0, h1, l1;
                    split_bf16(o0, h0, l0);
                    split_bf16(o1, h1, l1);
                    *(__nv_bfloat162*)(g_hbhi + ro + col) = __nv_bfloat162(h0, h1);
                    *(__nv_bfloat162*)(g_hblo + ro + col) = __nv_bfloat162(l0, l1);
                }
            }
        }
    }
}

// ---------------- launch ----------------
extern "C" void kernel_launch(void* const* d_in, const int* in_sizes, int n_in,
                              void* d_out, int out_size) {
    const float* x     = (const float*)d_in[0];
    const void*  ei    = d_in[1];
    const float* Wl    = (const float*)d_in[2];
    const float* bl    = (const float*)d_in[3];
    const float* Wr    = (const float*)d_in[4];
    const float* gamma = (const float*)d_in[5];
    const float* beta  = (const float*)d_in[6];
    float* out = (float*)d_out;

    static float* hdev = nullptr;
    if (!hdev) cudaGetSymbolAddress((void**)&hdev, g_h);

    k_detect<<<((2 * N_EDGES / 4) + 255) / 256, 256>>>((const uint4*)ei);
    k_count<<<(N_EDGES + 255) / 256, 256>>>(ei);
    k_scan_fill<<<SCAN_BLOCKS, 1024>>>(ei);
    k_convx<<<((N_NODES * DIM / 4) + 255) / 256, 256>>>((const float4*)x);
    k_convw<<<(NLAYERS * DIM * 2 * DIM + 255) / 256, 256>>>(Wl, Wr);

    for (int l = 0; l < NLAYERS; l++) {
        const float* hsrc = (l == 0) ? x : hdev;
        float* dstF = (l == NLAYERS - 1) ? out : hdev;
        int wbf = (l == NLAYERS - 1) ? 0 : 1;
        k_aggregate<<<(N_NODES + 7) / 8, 256>>>(hsrc);
        k_gemm_ln<<<(N_NODES + 127) / 128, 256>>>(
            l, bl + l * DIM, gamma + l * DIM, beta + l * DIM, dstF, wbf);
    }
}